// round 1
// baseline (speedup 1.0000x reference)
#include <cuda_runtime.h>

// Problem constants (derived from reference: W=400, H=352, D=5)
#define BB 2
#define CC 64
#define NN (64 * 2048)      // RH*RW = 131072 points per batch
#define WW 400
#define HH 352
#define DD 5
#define DWH (DD * WW * HH)  // 704000 cells per batch

// Scratch: winner point-index per (batch, cell). -1 = empty.
__device__ int g_winner[BB * DWH];

__global__ void init_winner_kernel() {
    int i = blockIdx.x * blockDim.x + threadIdx.x;
    int4* p = reinterpret_cast<int4*>(g_winner);
    if (i < (BB * DWH) / 4) {
        p[i] = make_int4(-1, -1, -1, -1);
    }
}

__global__ void scatter_winner_kernel(const float* __restrict__ xyz) {
    int t = blockIdx.x * blockDim.x + threadIdx.x;
    if (t >= BB * NN) return;
    int b = t >> 17;          // NN = 2^17
    int n = t & (NN - 1);

    const float xp = xyz[(b * 3 + 0) * NN + n];
    const float yp = xyz[(b * 3 + 1) * NN + n];
    const float zp = xyz[(b * 3 + 2) * NN + n];

    // valid z-bin (mode='drop': out-of-range zbin is dropped)
    if (!(zp >= -3.0f && zp < 1.0f)) return;
    int zbin = (int)floorf(__fdiv_rn(zp + 3.0f, 0.8f));
    if (zbin < 0 || zbin >= DD) return;

    // x_img = trunc(-yp/0.2) + 200, clip [0, W-1]
    int xi = (int)__fdiv_rn(-yp, 0.2f) + 200;
    xi = min(max(xi, 0), WW - 1);
    // y_img = trunc(-xp/0.2) + 352, clip [0, H-1]
    int yi = (int)__fdiv_rn(-xp, 0.2f) + 352;
    yi = min(max(yi, 0), HH - 1);

    int xf = WW - 1 - xi;
    int yf = HH - 1 - yi;
    int cell = (zbin * WW + xf) * HH + yf;

    // Last point index wins (XLA CPU scatter applies updates in order)
    atomicMax(&g_winner[b * DWH + cell], n);
}

// One thread per 4 consecutive output elements (inner dim H=352, DWH % 4 == 0).
// out layout: (B, C, D, W, H). For cell with winner p: out = range_res[b][c][p].
__global__ void write_bev_kernel(const float* __restrict__ feat,
                                 float* __restrict__ out) {
    long long v = (long long)blockIdx.x * blockDim.x + threadIdx.x;
    const long long total4 = (long long)BB * CC * DWH / 4;
    if (v >= total4) return;

    long long idx = v * 4;                 // element index
    int b = (int)(idx / ((long long)CC * DWH));
    long long rem = idx - (long long)b * CC * DWH;
    int c = (int)(rem / DWH);
    int cell = (int)(rem - (long long)c * DWH);

    const int4 w = *reinterpret_cast<const int4*>(&g_winner[b * DWH + cell]);
    const float* plane = feat + ((long long)b * CC + c) * NN;

    float4 r;
    r.x = (w.x >= 0) ? __ldg(plane + w.x) : 0.0f;
    r.y = (w.y >= 0) ? __ldg(plane + w.y) : 0.0f;
    r.z = (w.z >= 0) ? __ldg(plane + w.z) : 0.0f;
    r.w = (w.w >= 0) ? __ldg(plane + w.w) : 0.0f;

    *reinterpret_cast<float4*>(out + idx) = r;
}

extern "C" void kernel_launch(void* const* d_in, const int* in_sizes, int n_in,
                              void* d_out, int out_size) {
    const float* range_res = (const float*)d_in[0];   // (B, C, RH, RW)
    const float* xyz       = (const float*)d_in[1];   // (B, 3, RH, RW)
    float* out = (float*)d_out;                       // (B, C, D, W, H)

    // 1) winner map := -1
    {
        int n4 = (BB * DWH) / 4;
        init_winner_kernel<<<(n4 + 255) / 256, 256>>>();
    }
    // 2) resolve winners (last index wins)
    {
        int npts = BB * NN;
        scatter_winner_kernel<<<(npts + 255) / 256, 256>>>(xyz);
    }
    // 3) coalesced gather-write of the full output
    {
        long long total4 = (long long)BB * CC * DWH / 4;
        int blocks = (int)((total4 + 255) / 256);
        write_bev_kernel<<<blocks, 256>>>(range_res, out);
    }
}